// round 12
// baseline (speedup 1.0000x reference)
#include <cuda_runtime.h>
#include <cuda_fp16.h>
#include <math.h>

#define NN      100000
#define EE      1600000
#define DIN_    128
#define HID_    64
#define DOUT_   40
#define NLAYERS 8
#define NB1     ((NN + 511) / 512)   // 196 scan blocks

// ---------------- scratch (device globals; no allocation allowed) ----------
__device__ int    g_degi[NN];
__device__ float  g_dinv[NN];
__device__ int    g_off[NN];
__device__ int    g_cur[NN];
__device__ int    g_bsum[256];
__device__ int    g_boff[256];
__device__ uint2  g_edge[EE];       // {src, __float_as_uint(0.9*w)}
__device__ uint4  g_h0h[NN * 8];    // fp16 h: 64 halves/row = 8 uint4
__device__ uint4  g_hah[NN * 8];
__device__ uint4  g_hbh[NN * 8];
__device__ __half g_Mh[NLAYERS * HID_ * HID_];
__device__ __half g_W1h[DIN_ * HID_];

// ---------------- helpers ---------------------------------------------------
__device__ __forceinline__ void fma8(float* acc, uint4 u, float w) {
    float2 p;
    p = __half22float2(*(__half2*)&u.x); acc[0] += w * p.x; acc[1] += w * p.y;
    p = __half22float2(*(__half2*)&u.y); acc[2] += w * p.x; acc[3] += w * p.y;
    p = __half22float2(*(__half2*)&u.z); acc[4] += w * p.x; acc[5] += w * p.y;
    p = __half22float2(*(__half2*)&u.w); acc[6] += w * p.x; acc[7] += w * p.y;
}

__device__ __forceinline__ void ldsm_x4(unsigned* r, unsigned addr) {
    asm volatile("ldmatrix.sync.aligned.m8n8.x4.shared.b16 {%0,%1,%2,%3}, [%4];"
                 : "=r"(r[0]), "=r"(r[1]), "=r"(r[2]), "=r"(r[3]) : "r"(addr));
}
__device__ __forceinline__ void ldsm_x4_t(unsigned* r, unsigned addr) {
    asm volatile("ldmatrix.sync.aligned.m8n8.x4.trans.shared.b16 {%0,%1,%2,%3}, [%4];"
                 : "=r"(r[0]), "=r"(r[1]), "=r"(r[2]), "=r"(r[3]) : "r"(addr));
}
__device__ __forceinline__ void mma_f16(float* d, const unsigned* a, const unsigned* b) {
    asm volatile(
        "mma.sync.aligned.m16n8k16.row.col.f32.f16.f16.f32 "
        "{%0,%1,%2,%3}, {%4,%5,%6,%7}, {%8,%9}, {%0,%1,%2,%3};"
        : "+f"(d[0]), "+f"(d[1]), "+f"(d[2]), "+f"(d[3])
        : "r"(a[0]), "r"(a[1]), "r"(a[2]), "r"(a[3]), "r"(b[0]), "r"(b[1]));
}

// ---------------- graph prep (edge_index is INT32) -------------------------
__global__ void deg_zero_k() {
    int i = blockIdx.x * blockDim.x + threadIdx.x;
    if (i < NN) g_degi[i] = 0;
}

__global__ void deg_count_k(const int* __restrict__ ei) {
    int e = blockIdx.x * blockDim.x + threadIdx.x;
    if (e < EE) {
        int d = ei[EE + e];
        if (d >= 0 && d < NN) atomicAdd(&g_degi[d], 1);
    }
}

__global__ void dinv_k() {
    int i = blockIdx.x * blockDim.x + threadIdx.x;
    if (i < NN) g_dinv[i] = rsqrtf((float)g_degi[i] + 1.0f);  // +1 self-loop
}

__global__ void scan1_k() {
    __shared__ int s[1024];
    int t = threadIdx.x;
    int i = blockIdx.x * 512 + t;
    int v = (i < NN) ? g_degi[i] : 0;
    s[t] = 0;
    s[512 + t] = v;
    __syncthreads();
#pragma unroll
    for (int d = 1; d < 512; d <<= 1) {
        int u = s[512 + t - d];
        __syncthreads();
        s[512 + t] += u;
        __syncthreads();
    }
    if (i < NN) g_off[i] = s[512 + t] - v;
    if (t == 511) g_bsum[blockIdx.x] = s[512 + 511];
}

__global__ void scan2_k() {
    __shared__ int s[512];
    int t = threadIdx.x;
    int v = (t < NB1) ? g_bsum[t] : 0;
    s[t] = 0;
    s[256 + t] = v;
    __syncthreads();
#pragma unroll
    for (int d = 1; d < 256; d <<= 1) {
        int u = s[256 + t - d];
        __syncthreads();
        s[256 + t] += u;
        __syncthreads();
    }
    g_boff[t] = s[256 + t] - v;
}

__global__ void scan3_k() {
    int i = blockIdx.x * 512 + threadIdx.x;
    if (i < NN) {
        int o = g_off[i] + g_boff[blockIdx.x];
        g_off[i] = o;
        g_cur[i] = o;
    }
}

__global__ void fill_k(const int* __restrict__ ei) {
    int e = blockIdx.x * blockDim.x + threadIdx.x;
    if (e < EE) {
        int s = ei[e];
        int d = ei[EE + e];
        if (s >= 0 && s < NN && d >= 0 && d < NN) {
            int pos = atomicAdd(&g_cur[d], 1);
            uint2 pe;
            pe.x = (unsigned)s;
            pe.y = __float_as_uint(0.9f * g_dinv[s] * g_dinv[d]);
            g_edge[pos] = pe;
        }
    }
}

// M_l = (1-beta)*I + beta*W_l, stored fp16
__global__ void mfuse_k(const float* __restrict__ cw) {
    int idx = blockIdx.x * blockDim.x + threadIdx.x;
    if (idx < NLAYERS * HID_ * HID_) {
        int l = idx >> 12;
        int rc = idx & 4095;
        int r = rc >> 6, c = rc & 63;
        float beta = logf(0.5f / (float)(l + 1) + 1.0f);
        float v = beta * cw[idx];
        if (r == c) v += 1.0f - beta;
        g_Mh[idx] = __float2half(v);
    }
}

__global__ void w1conv_k(const float* __restrict__ W1) {
    int idx = blockIdx.x * blockDim.x + threadIdx.x;
    if (idx < DIN_ * HID_) g_W1h[idx] = __float2half(W1[idx]);
}

// ---------------- fused layer: warp-per-row gather + HMMA GEMM + relu ------
// 512 threads = 16 warps; block owns 64 rows; warp w handles rows 4w..4w+3.
// Within a row: 32 lanes = 4 edge-subgroups x 8 feature lanes.
__global__ void __launch_bounds__(512) layer_k(int layer) {
    __shared__ __align__(16) __half Ah[64 * 72];   // row-major, stride 72 halves
    __shared__ __align__(16) __half Bh[64 * 72];

    const uint4* __restrict__ hin =
        (layer == 0) ? g_h0h : ((layer & 1) ? g_hah : g_hbh);
    uint4* __restrict__ hout = (layer & 1) ? g_hbh : g_hah;

    int tid = threadIdx.x;
    int row0 = blockIdx.x << 6;
    int w = tid >> 5, lane = tid & 31;

    // load M_l (fp16) into Bh with padded stride
    {
        const unsigned* Mw = (const unsigned*)(g_Mh + layer * 4096);  // 2048 words
        unsigned* Bw = (unsigned*)Bh;
#pragma unroll
        for (int t = 0; t < 4; t++) {
            int v = t * 512 + tid;
            Bw[(v >> 5) * 36 + (v & 31)] = Mw[v];
        }
    }

    // ---- gather: warp-per-row ----
    int j8 = lane & 7;          // feature uint4 index (16B each)
    int eg = lane >> 3;         // edge subgroup 0..3
#pragma unroll
    for (int rr = 0; rr < 4; rr++) {
        int rl = (w << 2) | rr;
        int row = row0 + rl;
        float acc[8] = {0.f, 0.f, 0.f, 0.f, 0.f, 0.f, 0.f, 0.f};
        if (row < NN) {
            int beg = g_off[row];
            int deg = g_degi[row];
            const uint2* ep = g_edge + beg;
            int e = eg;
            for (; e + 4 < deg; e += 8) {
                uint2 q0 = ep[e];
                uint2 q1 = ep[e + 4];
                uint4 v0 = hin[q0.x * 8 + j8];
                uint4 v1 = hin[q1.x * 8 + j8];
                fma8(acc, v0, __uint_as_float(q0.y));
                fma8(acc, v1, __uint_as_float(q1.y));
            }
            if (e < deg) {
                uint2 q0 = ep[e];
                fma8(acc, hin[q0.x * 8 + j8], __uint_as_float(q0.y));
            }
            if (eg == 0) {
                float di = g_dinv[row];
                fma8(acc, hin[row * 8 + j8], 0.9f * di * di);
                fma8(acc, g_h0h[row * 8 + j8], 0.1f);
            }
        }
        // reduce the 4 edge-subgroups
#pragma unroll
        for (int i = 0; i < 8; i++) {
            acc[i] += __shfl_xor_sync(0xffffffff, acc[i], 8);
            acc[i] += __shfl_xor_sync(0xffffffff, acc[i], 16);
        }
        if (eg == 0) {
            __half2 p0 = __floats2half2_rn(acc[0], acc[1]);
            __half2 p1 = __floats2half2_rn(acc[2], acc[3]);
            __half2 p2 = __floats2half2_rn(acc[4], acc[5]);
            __half2 p3 = __floats2half2_rn(acc[6], acc[7]);
            uint4 st;
            st.x = *(unsigned*)&p0; st.y = *(unsigned*)&p1;
            st.z = *(unsigned*)&p2; st.w = *(unsigned*)&p3;
            *(uint4*)(Ah + rl * 72 + j8 * 8) = st;
        }
    }
    __syncthreads();

    // ---- HMMA: 16 warps, each 16x16 tile ----
    int r0 = (w & 3) * 16;
    int n0 = (w >> 2) * 16;
    float d0[4] = {}, d1[4] = {};

    unsigned Asm = (unsigned)__cvta_generic_to_shared(Ah);
    unsigned Bsm = (unsigned)__cvta_generic_to_shared(Bh);
    int lr = lane & 15, lh = lane >> 4;
#pragma unroll
    for (int ks = 0; ks < 4; ks++) {
        int kk = ks * 16;
        unsigned a[4], b[4];
        ldsm_x4(a, Asm + ((r0 + lr) * 72 + kk + lh * 8) * 2);
        ldsm_x4_t(b, Bsm + ((kk + lr) * 72 + n0 + lh * 8) * 2);
        mma_f16(d0, a, b + 0);
        mma_f16(d1, a, b + 2);
    }

    // epilogue: relu, pack fp16, store
    int tg = lane >> 2, ti = lane & 3;
    unsigned* ho = (unsigned*)hout;   // 32 words per row
    int grow0 = row0 + r0 + tg;
    int grow1 = grow0 + 8;
    {
        int col = n0 + ti * 2;
        __half2 lo = __floats2half2_rn(fmaxf(d0[0], 0.f), fmaxf(d0[1], 0.f));
        __half2 hi = __floats2half2_rn(fmaxf(d0[2], 0.f), fmaxf(d0[3], 0.f));
        if (grow0 < NN) ho[grow0 * 32 + (col >> 1)] = *(unsigned*)&lo;
        if (grow1 < NN) ho[grow1 * 32 + (col >> 1)] = *(unsigned*)&hi;
        col += 8;
        lo = __floats2half2_rn(fmaxf(d1[0], 0.f), fmaxf(d1[1], 0.f));
        hi = __floats2half2_rn(fmaxf(d1[2], 0.f), fmaxf(d1[3], 0.f));
        if (grow0 < NN) ho[grow0 * 32 + (col >> 1)] = *(unsigned*)&lo;
        if (grow1 < NN) ho[grow1 * 32 + (col >> 1)] = *(unsigned*)&hi;
    }
}

// ---------------- GEMM1: h0 = relu(x @ W1 + b1), HMMA, K=128 ---------------
__global__ void __launch_bounds__(256) gemm1_k(
    const float* __restrict__ x, const float* __restrict__ bias)
{
    __shared__ __align__(16) __half Ah[64 * 72];
    __shared__ __align__(16) __half Bh[64 * 72];
    __shared__ float bsh[64];

    int tid = threadIdx.x;
    int row0 = blockIdx.x << 6;
    if (tid < 64) bsh[tid] = bias[tid];

    int w = tid >> 5, lane = tid & 31;
    int r0 = (w & 3) * 16;
    int n0 = (w >> 2) * 32;
    int lr = lane & 15, lh = lane >> 4;
    float d0[4] = {}, d1[4] = {}, d2[4] = {}, d3[4] = {};

    unsigned Asm = (unsigned)__cvta_generic_to_shared(Ah);
    unsigned Bsm = (unsigned)__cvta_generic_to_shared(Bh);

#pragma unroll
    for (int kc = 0; kc < 128; kc += 64) {
        {
            const unsigned* Ww = (const unsigned*)(g_W1h + kc * 64);
            unsigned* Bw = (unsigned*)Bh;
#pragma unroll
            for (int t = 0; t < 8; t++) {
                int v = t * 256 + tid;
                Bw[(v >> 5) * 36 + (v & 31)] = Ww[v];
            }
        }
        {
            int r = tid >> 2, q = tid & 3;
            int grow = row0 + r;
            float4 f0 = make_float4(0, 0, 0, 0), f1 = f0, f2 = f0, f3 = f0;
            if (grow < NN) {
                const float4* xr = (const float4*)x + grow * 32 + (kc >> 2) + q * 4;
                f0 = xr[0]; f1 = xr[1]; f2 = xr[2]; f3 = xr[3];
            }
            __half2 h0_ = __floats2half2_rn(f0.x, f0.y);
            __half2 h1_ = __floats2half2_rn(f0.z, f0.w);
            __half2 h2_ = __floats2half2_rn(f1.x, f1.y);
            __half2 h3_ = __floats2half2_rn(f1.z, f1.w);
            __half2 h4_ = __floats2half2_rn(f2.x, f2.y);
            __half2 h5_ = __floats2half2_rn(f2.z, f2.w);
            __half2 h6_ = __floats2half2_rn(f3.x, f3.y);
            __half2 h7_ = __floats2half2_rn(f3.z, f3.w);
            uint4 s0, s1;
            s0.x = *(unsigned*)&h0_; s0.y = *(unsigned*)&h1_;
            s0.z = *(unsigned*)&h2_; s0.w = *(unsigned*)&h3_;
            s1.x = *(unsigned*)&h4_; s1.y = *(unsigned*)&h5_;
            s1.z = *(unsigned*)&h6_; s1.w = *(unsigned*)&h7_;
            *(uint4*)(Ah + r * 72 + q * 16) = s0;
            *(uint4*)(Ah + r * 72 + q * 16 + 8) = s1;
        }
        __syncthreads();

#pragma unroll
        for (int ks = 0; ks < 4; ks++) {
            int kk = ks * 16;
            unsigned a[4], b0[4], b1[4];
            ldsm_x4(a, Asm + ((r0 + lr) * 72 + kk + lh * 8) * 2);
            unsigned bad = Bsm + ((kk + lr) * 72 + n0 + lh * 8) * 2;
            ldsm_x4_t(b0, bad);
            ldsm_x4_t(b1, bad + 32);
            mma_f16(d0, a, b0 + 0);
            mma_f16(d1, a, b0 + 2);
            mma_f16(d2, a, b1 + 0);
            mma_f16(d3, a, b1 + 2);
        }
        __syncthreads();
    }

    int tg = lane >> 2, ti = lane & 3;
    unsigned* ho = (unsigned*)g_h0h;
    int grow0 = row0 + r0 + tg;
    int grow1 = grow0 + 8;
    float* dd[4] = {d0, d1, d2, d3};
#pragma unroll
    for (int t = 0; t < 4; t++) {
        int col = n0 + t * 8 + ti * 2;
        float bx = bsh[col], by = bsh[col + 1];
        __half2 lo = __floats2half2_rn(fmaxf(dd[t][0] + bx, 0.f), fmaxf(dd[t][1] + by, 0.f));
        __half2 hi = __floats2half2_rn(fmaxf(dd[t][2] + bx, 0.f), fmaxf(dd[t][3] + by, 0.f));
        if (grow0 < NN) ho[grow0 * 32 + (col >> 1)] = *(unsigned*)&lo;
        if (grow1 < NN) ho[grow1 * 32 + (col >> 1)] = *(unsigned*)&hi;
    }
}

// ---------------- final GEMM: out = h @ W2 + b2  ([N,64]@[64,40]) ----------
__device__ __forceinline__ float4 u2f4(uint2 u) {
    __half2 a = *(__half2*)&u.x;
    __half2 b = *(__half2*)&u.y;
    float2 fa = __half22float2(a), fb = __half22float2(b);
    return make_float4(fa.x, fa.y, fb.x, fb.y);
}

__global__ void __launch_bounds__(256) final_k(
    const float* __restrict__ W2, const float* __restrict__ b2,
    float* __restrict__ out)
{
    __shared__ float W2s[64 * 40];
    __shared__ float b2s[40];
    int tid = threadIdx.x;
    for (int i = tid; i < 64 * 40; i += 256) W2s[i] = W2[i];
    if (tid < 40) b2s[tid] = b2[tid];
    __syncthreads();

    int row = blockIdx.x * 256 + tid;
    if (row >= NN) return;

    float acc[40];
#pragma unroll
    for (int j = 0; j < 40; j++) acc[j] = b2s[j];

    // last layer is 7 (odd) -> wrote g_hbh
    const uint4* hr = g_hbh + row * 8;
#pragma unroll
    for (int q = 0; q < 8; q++) {
        uint4 u = hr[q];
        float4 f0 = u2f4(make_uint2(u.x, u.y));
        float4 f1 = u2f4(make_uint2(u.z, u.w));
        float hs[8] = {f0.x, f0.y, f0.z, f0.w, f1.x, f1.y, f1.z, f1.w};
#pragma unroll
        for (int kk = 0; kk < 8; kk++) {
            const float* wrow = &W2s[(q * 8 + kk) * 40];
#pragma unroll
            for (int jj = 0; jj < 40; jj++)
                acc[jj] += hs[kk] * wrow[jj];
        }
    }
#pragma unroll
    for (int jj = 0; jj < 40; jj++)
        out[row * 40 + jj] = acc[jj];
}

// ---------------- launch ---------------------------------------------------
extern "C" void kernel_launch(void* const* d_in, const int* in_sizes, int n_in,
                              void* d_out, int out_size) {
    const float* x  = (const float*)d_in[0];
    const int*   ei = (const int*)d_in[1];     // int32 (jax default, no x64)
    const float* W1 = (const float*)d_in[2];
    const float* b1 = (const float*)d_in[3];
    const float* cw = (const float*)d_in[4];
    const float* W2 = (const float*)d_in[5];
    const float* b2 = (const float*)d_in[6];
    float*       out = (float*)d_out;

    deg_zero_k<<<(NN + 255) / 256, 256>>>();
    deg_count_k<<<(EE + 255) / 256, 256>>>(ei);
    dinv_k<<<(NN + 255) / 256, 256>>>();
    scan1_k<<<NB1, 512>>>();
    scan2_k<<<1, 256>>>();
    scan3_k<<<NB1, 512>>>();
    fill_k<<<(EE + 255) / 256, 256>>>(ei);
    mfuse_k<<<(NLAYERS * HID_ * HID_ + 255) / 256, 256>>>(cw);
    w1conv_k<<<(DIN_ * HID_ + 255) / 256, 256>>>(W1);

    gemm1_k<<<(NN + 63) / 64, 256>>>(x, b1);

    for (int l = 0; l < NLAYERS; l++)
        layer_k<<<(NN + 63) / 64, 512>>>(l);   // 512 threads — matches kernel!

    final_k<<<(NN + 255) / 256, 256>>>(W2, b2, out);
}

// round 14
// speedup vs baseline: 1.1419x; 1.1419x over previous
#include <cuda_runtime.h>
#include <cuda_fp16.h>
#include <math.h>

#define NN      100000
#define EE      1600000
#define DIN_    128
#define HID_    64
#define DOUT_   40
#define NLAYERS 8
#define NB1     ((NN + 511) / 512)   // 196 scan blocks

// ---------------- scratch (device globals; no allocation allowed) ----------
__device__ int    g_degi[NN];
__device__ float  g_dinv[NN];
__device__ int    g_off[NN];
__device__ int    g_cur[NN];
__device__ int    g_bsum[256];
__device__ int    g_boff[256];
__device__ uint2  g_edge[EE];       // {src, __float_as_uint(0.9*w)}
__device__ uint4  g_h0h[NN * 8];    // fp16 h: 64 halves/row = 8 uint4
__device__ uint4  g_hah[NN * 8];
__device__ uint4  g_hbh[NN * 8];
__device__ __half g_Mh[NLAYERS * HID_ * HID_];
__device__ __half g_W1h[DIN_ * HID_];

// ---------------- helpers ---------------------------------------------------
__device__ __forceinline__ void fma8(float* acc, uint4 u, float w) {
    float2 p;
    p = __half22float2(*(__half2*)&u.x); acc[0] += w * p.x; acc[1] += w * p.y;
    p = __half22float2(*(__half2*)&u.y); acc[2] += w * p.x; acc[3] += w * p.y;
    p = __half22float2(*(__half2*)&u.z); acc[4] += w * p.x; acc[5] += w * p.y;
    p = __half22float2(*(__half2*)&u.w); acc[6] += w * p.x; acc[7] += w * p.y;
}

__device__ __forceinline__ void ldsm_x4(unsigned* r, unsigned addr) {
    asm volatile("ldmatrix.sync.aligned.m8n8.x4.shared.b16 {%0,%1,%2,%3}, [%4];"
                 : "=r"(r[0]), "=r"(r[1]), "=r"(r[2]), "=r"(r[3]) : "r"(addr));
}
__device__ __forceinline__ void ldsm_x4_t(unsigned* r, unsigned addr) {
    asm volatile("ldmatrix.sync.aligned.m8n8.x4.trans.shared.b16 {%0,%1,%2,%3}, [%4];"
                 : "=r"(r[0]), "=r"(r[1]), "=r"(r[2]), "=r"(r[3]) : "r"(addr));
}
__device__ __forceinline__ void mma_f16(float* d, const unsigned* a, const unsigned* b) {
    asm volatile(
        "mma.sync.aligned.m16n8k16.row.col.f32.f16.f16.f32 "
        "{%0,%1,%2,%3}, {%4,%5,%6,%7}, {%8,%9}, {%0,%1,%2,%3};"
        : "+f"(d[0]), "+f"(d[1]), "+f"(d[2]), "+f"(d[3])
        : "r"(a[0]), "r"(a[1]), "r"(a[2]), "r"(a[3]), "r"(b[0]), "r"(b[1]));
}

// ---------------- graph prep (edge_index is INT32) -------------------------
__global__ void deg_zero_k() {
    int i = blockIdx.x * blockDim.x + threadIdx.x;
    if (i < NN) g_degi[i] = 0;
}

__global__ void deg_count_k(const int* __restrict__ ei) {
    int e = blockIdx.x * blockDim.x + threadIdx.x;
    if (e < EE) {
        int d = ei[EE + e];
        if (d >= 0 && d < NN) atomicAdd(&g_degi[d], 1);
    }
}

__global__ void dinv_k() {
    int i = blockIdx.x * blockDim.x + threadIdx.x;
    if (i < NN) g_dinv[i] = rsqrtf((float)g_degi[i] + 1.0f);  // +1 self-loop
}

__global__ void scan1_k() {
    __shared__ int s[1024];
    int t = threadIdx.x;
    int i = blockIdx.x * 512 + t;
    int v = (i < NN) ? g_degi[i] : 0;
    s[t] = 0;
    s[512 + t] = v;
    __syncthreads();
#pragma unroll
    for (int d = 1; d < 512; d <<= 1) {
        int u = s[512 + t - d];
        __syncthreads();
        s[512 + t] += u;
        __syncthreads();
    }
    if (i < NN) g_off[i] = s[512 + t] - v;
    if (t == 511) g_bsum[blockIdx.x] = s[512 + 511];
}

__global__ void scan2_k() {
    __shared__ int s[512];
    int t = threadIdx.x;
    int v = (t < NB1) ? g_bsum[t] : 0;
    s[t] = 0;
    s[256 + t] = v;
    __syncthreads();
#pragma unroll
    for (int d = 1; d < 256; d <<= 1) {
        int u = s[256 + t - d];
        __syncthreads();
        s[256 + t] += u;
        __syncthreads();
    }
    g_boff[t] = s[256 + t] - v;
}

__global__ void scan3_k() {
    int i = blockIdx.x * 512 + threadIdx.x;
    if (i < NN) {
        int o = g_off[i] + g_boff[blockIdx.x];
        g_off[i] = o;
        g_cur[i] = o;
    }
}

__global__ void fill_k(const int* __restrict__ ei) {
    int e = blockIdx.x * blockDim.x + threadIdx.x;
    if (e < EE) {
        int s = ei[e];
        int d = ei[EE + e];
        if (s >= 0 && s < NN && d >= 0 && d < NN) {
            int pos = atomicAdd(&g_cur[d], 1);
            uint2 pe;
            pe.x = (unsigned)s;
            pe.y = __float_as_uint(0.9f * g_dinv[s] * g_dinv[d]);
            g_edge[pos] = pe;
        }
    }
}

// M_l = (1-beta)*I + beta*W_l, stored fp16
__global__ void mfuse_k(const float* __restrict__ cw) {
    int idx = blockIdx.x * blockDim.x + threadIdx.x;
    if (idx < NLAYERS * HID_ * HID_) {
        int l = idx >> 12;
        int rc = idx & 4095;
        int r = rc >> 6, c = rc & 63;
        float beta = logf(0.5f / (float)(l + 1) + 1.0f);
        float v = beta * cw[idx];
        if (r == c) v += 1.0f - beta;
        g_Mh[idx] = __float2half(v);
    }
}

__global__ void w1conv_k(const float* __restrict__ W1) {
    int idx = blockIdx.x * blockDim.x + threadIdx.x;
    if (idx < DIN_ * HID_) g_W1h[idx] = __float2half(W1[idx]);
}

// ---------------- fused layer: gather (MLP-8) + HMMA GEMM + relu -----------
// 256 threads; 8 lanes/row (uint4 feature slice), 32 rows/pass, 2 passes.
__global__ void __launch_bounds__(256) layer_k(int layer) {
    __shared__ __align__(16) __half Ah[64 * 72];   // row-major, stride 72 halves
    __shared__ __align__(16) __half Bh[64 * 72];

    const uint4* __restrict__ hin =
        (layer == 0) ? g_h0h : ((layer & 1) ? g_hah : g_hbh);
    uint4* __restrict__ hout = (layer & 1) ? g_hbh : g_hah;

    int tid = threadIdx.x;
    int row0 = blockIdx.x << 6;

    // load M_l (fp16) into Bh with padded stride
    {
        const unsigned* Mw = (const unsigned*)(g_Mh + layer * 4096);  // 2048 words
        unsigned* Bw = (unsigned*)Bh;
#pragma unroll
        for (int t = 0; t < 8; t++) {
            int v = t * 256 + tid;
            Bw[(v >> 5) * 36 + (v & 31)] = Mw[v];
        }
    }

    // gather: 8 lanes/row, uint4 (16B) per lane; 2 passes of 32 rows
    int j = tid & 7;
    int rbase = tid >> 3;
#pragma unroll
    for (int p = 0; p < 2; p++) {
        int rl = p * 32 + rbase;
        int row = row0 + rl;
        float acc[8] = {0.f, 0.f, 0.f, 0.f, 0.f, 0.f, 0.f, 0.f};
        if (row < NN) {
            float di = g_dinv[row];
            fma8(acc, hin[row * 8 + j], 0.9f * di * di);

            int beg = g_off[row];
            int deg = g_degi[row];
            const uint2* ep = g_edge + beg;
            int e = 0;
            // unroll-8: 8 edge descriptors then 8 gathers in flight
            for (; e + 7 < deg; e += 8) {
                uint2 q0 = ep[e],     q1 = ep[e + 1], q2 = ep[e + 2], q3 = ep[e + 3];
                uint2 q4 = ep[e + 4], q5 = ep[e + 5], q6 = ep[e + 6], q7 = ep[e + 7];
                uint4 v0 = hin[q0.x * 8 + j];
                uint4 v1 = hin[q1.x * 8 + j];
                uint4 v2 = hin[q2.x * 8 + j];
                uint4 v3 = hin[q3.x * 8 + j];
                uint4 v4 = hin[q4.x * 8 + j];
                uint4 v5 = hin[q5.x * 8 + j];
                uint4 v6 = hin[q6.x * 8 + j];
                uint4 v7 = hin[q7.x * 8 + j];
                fma8(acc, v0, __uint_as_float(q0.y));
                fma8(acc, v1, __uint_as_float(q1.y));
                fma8(acc, v2, __uint_as_float(q2.y));
                fma8(acc, v3, __uint_as_float(q3.y));
                fma8(acc, v4, __uint_as_float(q4.y));
                fma8(acc, v5, __uint_as_float(q5.y));
                fma8(acc, v6, __uint_as_float(q6.y));
                fma8(acc, v7, __uint_as_float(q7.y));
            }
            for (; e + 1 < deg; e += 2) {
                uint2 q0 = ep[e], q1 = ep[e + 1];
                uint4 v0 = hin[q0.x * 8 + j];
                uint4 v1 = hin[q1.x * 8 + j];
                fma8(acc, v0, __uint_as_float(q0.y));
                fma8(acc, v1, __uint_as_float(q1.y));
            }
            if (e < deg) {
                uint2 q0 = ep[e];
                fma8(acc, hin[q0.x * 8 + j], __uint_as_float(q0.y));
            }
            fma8(acc, g_h0h[row * 8 + j], 0.1f);
        }
        __half2 p0 = __floats2half2_rn(acc[0], acc[1]);
        __half2 p1 = __floats2half2_rn(acc[2], acc[3]);
        __half2 p2 = __floats2half2_rn(acc[4], acc[5]);
        __half2 p3 = __floats2half2_rn(acc[6], acc[7]);
        uint4 st;
        st.x = *(unsigned*)&p0; st.y = *(unsigned*)&p1;
        st.z = *(unsigned*)&p2; st.w = *(unsigned*)&p3;
        *(uint4*)(Ah + rl * 72 + j * 8) = st;
    }
    __syncthreads();

    // HMMA: 8 warps, each 16x32 tile
    int w = tid >> 5, lane = tid & 31;
    int r0 = (w & 3) * 16;
    int n0 = (w >> 2) * 32;
    float d0[4] = {}, d1[4] = {}, d2[4] = {}, d3[4] = {};

    unsigned Asm = (unsigned)__cvta_generic_to_shared(Ah);
    unsigned Bsm = (unsigned)__cvta_generic_to_shared(Bh);
    int lr = lane & 15, lh = lane >> 4;
#pragma unroll
    for (int ks = 0; ks < 4; ks++) {
        int kk = ks * 16;
        unsigned a[4], b0[4], b1[4];
        ldsm_x4(a, Asm + ((r0 + lr) * 72 + kk + lh * 8) * 2);
        unsigned bad = Bsm + ((kk + lr) * 72 + n0 + lh * 8) * 2;
        ldsm_x4_t(b0, bad);
        ldsm_x4_t(b1, bad + 32);
        mma_f16(d0, a, b0 + 0);
        mma_f16(d1, a, b0 + 2);
        mma_f16(d2, a, b1 + 0);
        mma_f16(d3, a, b1 + 2);
    }

    // epilogue: relu, pack fp16, store
    int tg = lane >> 2, ti = lane & 3;
    unsigned* ho = (unsigned*)hout;   // 32 words per row
    int grow0 = row0 + r0 + tg;
    int grow1 = grow0 + 8;
    float* dd[4] = {d0, d1, d2, d3};
#pragma unroll
    for (int t = 0; t < 4; t++) {
        int col = n0 + t * 8 + ti * 2;
        __half2 lo = __floats2half2_rn(fmaxf(dd[t][0], 0.f), fmaxf(dd[t][1], 0.f));
        __half2 hi = __floats2half2_rn(fmaxf(dd[t][2], 0.f), fmaxf(dd[t][3], 0.f));
        if (grow0 < NN) ho[grow0 * 32 + (col >> 1)] = *(unsigned*)&lo;
        if (grow1 < NN) ho[grow1 * 32 + (col >> 1)] = *(unsigned*)&hi;
    }
}

// ---------------- GEMM1: h0 = relu(x @ W1 + b1), HMMA, K=128 ---------------
__global__ void __launch_bounds__(256) gemm1_k(
    const float* __restrict__ x, const float* __restrict__ bias)
{
    __shared__ __align__(16) __half Ah[64 * 72];
    __shared__ __align__(16) __half Bh[64 * 72];
    __shared__ float bsh[64];

    int tid = threadIdx.x;
    int row0 = blockIdx.x << 6;
    if (tid < 64) bsh[tid] = bias[tid];

    int w = tid >> 5, lane = tid & 31;
    int r0 = (w & 3) * 16;
    int n0 = (w >> 2) * 32;
    int lr = lane & 15, lh = lane >> 4;
    float d0[4] = {}, d1[4] = {}, d2[4] = {}, d3[4] = {};

    unsigned Asm = (unsigned)__cvta_generic_to_shared(Ah);
    unsigned Bsm = (unsigned)__cvta_generic_to_shared(Bh);

#pragma unroll
    for (int kc = 0; kc < 128; kc += 64) {
        {
            const unsigned* Ww = (const unsigned*)(g_W1h + kc * 64);
            unsigned* Bw = (unsigned*)Bh;
#pragma unroll
            for (int t = 0; t < 8; t++) {
                int v = t * 256 + tid;
                Bw[(v >> 5) * 36 + (v & 31)] = Ww[v];
            }
        }
        {
            int r = tid >> 2, q = tid & 3;
            int grow = row0 + r;
            float4 f0 = make_float4(0, 0, 0, 0), f1 = f0, f2 = f0, f3 = f0;
            if (grow < NN) {
                const float4* xr = (const float4*)x + grow * 32 + (kc >> 2) + q * 4;
                f0 = xr[0]; f1 = xr[1]; f2 = xr[2]; f3 = xr[3];
            }
            __half2 h0_ = __floats2half2_rn(f0.x, f0.y);
            __half2 h1_ = __floats2half2_rn(f0.z, f0.w);
            __half2 h2_ = __floats2half2_rn(f1.x, f1.y);
            __half2 h3_ = __floats2half2_rn(f1.z, f1.w);
            __half2 h4_ = __floats2half2_rn(f2.x, f2.y);
            __half2 h5_ = __floats2half2_rn(f2.z, f2.w);
            __half2 h6_ = __floats2half2_rn(f3.x, f3.y);
            __half2 h7_ = __floats2half2_rn(f3.z, f3.w);
            uint4 s0, s1;
            s0.x = *(unsigned*)&h0_; s0.y = *(unsigned*)&h1_;
            s0.z = *(unsigned*)&h2_; s0.w = *(unsigned*)&h3_;
            s1.x = *(unsigned*)&h4_; s1.y = *(unsigned*)&h5_;
            s1.z = *(unsigned*)&h6_; s1.w = *(unsigned*)&h7_;
            *(uint4*)(Ah + r * 72 + q * 16) = s0;
            *(uint4*)(Ah + r * 72 + q * 16 + 8) = s1;
        }
        __syncthreads();

#pragma unroll
        for (int ks = 0; ks < 4; ks++) {
            int kk = ks * 16;
            unsigned a[4], b0[4], b1[4];
            ldsm_x4(a, Asm + ((r0 + lr) * 72 + kk + lh * 8) * 2);
            unsigned bad = Bsm + ((kk + lr) * 72 + n0 + lh * 8) * 2;
            ldsm_x4_t(b0, bad);
            ldsm_x4_t(b1, bad + 32);
            mma_f16(d0, a, b0 + 0);
            mma_f16(d1, a, b0 + 2);
            mma_f16(d2, a, b1 + 0);
            mma_f16(d3, a, b1 + 2);
        }
        __syncthreads();
    }

    int tg = lane >> 2, ti = lane & 3;
    unsigned* ho = (unsigned*)g_h0h;
    int grow0 = row0 + r0 + tg;
    int grow1 = grow0 + 8;
    float* dd[4] = {d0, d1, d2, d3};
#pragma unroll
    for (int t = 0; t < 4; t++) {
        int col = n0 + t * 8 + ti * 2;
        float bx = bsh[col], by = bsh[col + 1];
        __half2 lo = __floats2half2_rn(fmaxf(dd[t][0] + bx, 0.f), fmaxf(dd[t][1] + by, 0.f));
        __half2 hi = __floats2half2_rn(fmaxf(dd[t][2] + bx, 0.f), fmaxf(dd[t][3] + by, 0.f));
        if (grow0 < NN) ho[grow0 * 32 + (col >> 1)] = *(unsigned*)&lo;
        if (grow1 < NN) ho[grow1 * 32 + (col >> 1)] = *(unsigned*)&hi;
    }
}

// ---------------- final GEMM: out = h @ W2 + b2  ([N,64]@[64,40]) ----------
__device__ __forceinline__ float4 u2f4(uint2 u) {
    __half2 a = *(__half2*)&u.x;
    __half2 b = *(__half2*)&u.y;
    float2 fa = __half22float2(a), fb = __half22float2(b);
    return make_float4(fa.x, fa.y, fb.x, fb.y);
}

__global__ void __launch_bounds__(256) final_k(
    const float* __restrict__ W2, const float* __restrict__ b2,
    float* __restrict__ out)
{
    __shared__ float W2s[64 * 40];
    __shared__ float b2s[40];
    int tid = threadIdx.x;
    for (int i = tid; i < 64 * 40; i += 256) W2s[i] = W2[i];
    if (tid < 40) b2s[tid] = b2[tid];
    __syncthreads();

    int row = blockIdx.x * 256 + tid;
    if (row >= NN) return;

    float acc[40];
#pragma unroll
    for (int j = 0; j < 40; j++) acc[j] = b2s[j];

    // last layer is 7 (odd) -> wrote g_hbh
    const uint4* hr = g_hbh + row * 8;
#pragma unroll
    for (int q = 0; q < 8; q++) {
        uint4 u = hr[q];
        float4 f0 = u2f4(make_uint2(u.x, u.y));
        float4 f1 = u2f4(make_uint2(u.z, u.w));
        float hs[8] = {f0.x, f0.y, f0.z, f0.w, f1.x, f1.y, f1.z, f1.w};
#pragma unroll
        for (int kk = 0; kk < 8; kk++) {
            const float* wrow = &W2s[(q * 8 + kk) * 40];
#pragma unroll
            for (int jj = 0; jj < 40; jj++)
                acc[jj] += hs[kk] * wrow[jj];
        }
    }
#pragma unroll
    for (int jj = 0; jj < 40; jj++)
        out[row * 40 + jj] = acc[jj];
}

// ---------------- launch ---------------------------------------------------
extern "C" void kernel_launch(void* const* d_in, const int* in_sizes, int n_in,
                              void* d_out, int out_size) {
    const float* x  = (const float*)d_in[0];
    const int*   ei = (const int*)d_in[1];     // int32 (jax default, no x64)
    const float* W1 = (const float*)d_in[2];
    const float* b1 = (const float*)d_in[3];
    const float* cw = (const float*)d_in[4];
    const float* W2 = (const float*)d_in[5];
    const float* b2 = (const float*)d_in[6];
    float*       out = (float*)d_out;

    deg_zero_k<<<(NN + 255) / 256, 256>>>();
    deg_count_k<<<(EE + 255) / 256, 256>>>(ei);
    dinv_k<<<(NN + 255) / 256, 256>>>();
    scan1_k<<<NB1, 512>>>();
    scan2_k<<<1, 256>>>();
    scan3_k<<<NB1, 512>>>();
    fill_k<<<(EE + 255) / 256, 256>>>(ei);
    mfuse_k<<<(NLAYERS * HID_ * HID_ + 255) / 256, 256>>>(cw);
    w1conv_k<<<(DIN_ * HID_ + 255) / 256, 256>>>(W1);

    gemm1_k<<<(NN + 63) / 64, 256>>>(x, b1);

    for (int l = 0; l < NLAYERS; l++)
        layer_k<<<(NN + 63) / 64, 256>>>(l);

    final_k<<<(NN + 255) / 256, 256>>>(W2, b2, out);
}